// round 14
// baseline (speedup 1.0000x reference)
#include <cuda_runtime.h>
#include <cuda_fp16.h>
#include <cstdint>

#define HID    128
#define NS_CAP 100096
#define NC_CAP 20096
#define NB_CAP 512
#define REC_CAP 1250000
#define CROW 272                         // padded course row bytes in smem (bank shift)

__device__ uint32_t g_h[(NS_CAP + NC_CAP) * 64];  // fp16 h tables (f16x2 words)
__device__ int   g_cnt[NB_CAP];
__device__ int   g_off[NB_CAP + 1];
__device__ int   g_cur[NB_CAP];
__device__ uint2 g_rec[REC_CAP];

// ---------------- helpers ----------------
__device__ __forceinline__ uint32_t smem_u32(const void* p) {
    uint32_t a;
    asm("{ .reg .u64 t; cvta.to.shared.u64 t, %1; cvt.u32.u64 %0, t; }" : "=r"(a) : "l"(p));
    return a;
}
__device__ __forceinline__ uint32_t hfpair(float lo, float hi) {
    uint32_t r;
    asm("cvt.rn.f16x2.f32 %0, %1, %2;" : "=r"(r) : "f"(hi), "f"(lo));
    return r;
}
__device__ __forceinline__ void ldmat4(uint32_t (&r)[4], uint32_t addr) {
    asm volatile("ldmatrix.sync.aligned.m8n8.x4.shared.b16 {%0,%1,%2,%3}, [%4];"
                 : "=r"(r[0]), "=r"(r[1]), "=r"(r[2]), "=r"(r[3]) : "r"(addr));
}
__device__ __forceinline__ void mma16816(float (&d)[4], const uint32_t (&a)[4],
                                         uint32_t b0, uint32_t b1) {
    asm volatile("mma.sync.aligned.m16n8k16.row.col.f32.f16.f16.f32 "
                 "{%0,%1,%2,%3}, {%4,%5,%6,%7}, {%8,%9}, {%0,%1,%2,%3};"
                 : "+f"(d[0]), "+f"(d[1]), "+f"(d[2]), "+f"(d[3])
                 : "r"(a[0]), "r"(a[1]), "r"(a[2]), "r"(a[3]), "r"(b0), "r"(b1));
}

// ---------------- 1) persistent node GEMM (zeros bucket counters too) ----------------
#define GROWS 64
#define SR2   256
__global__ void __launch_bounds__(128)
gemm_pre(const float* __restrict__ zs, const float* __restrict__ zc,
         const float* __restrict__ W1, const float* __restrict__ b1f,
         int nS, int nC, int nsU, int gridS, int gridC) {
    __shared__ __align__(16) char sA[GROWS * SR2];

    if (blockIdx.x == 0) {
        for (int i = threadIdx.x; i < NB_CAP; i += blockDim.x) g_cnt[i] = 0;
    }

    const bool isC  = blockIdx.x >= (unsigned)gridS;
    const int  tid0 = isC ? (blockIdx.x - gridS) : blockIdx.x;
    const int  tstr = isC ? gridC : gridS;
    const int  nrows = isC ? nC : nS;
    const int  nTiles = (nrows + GROWS - 1) / GROWS;
    const float* ztab = isC ? zc : zs;
    uint32_t*    htab = g_h + (isC ? (size_t)nsU : 0);
    const int kofs = isC ? HID : 0;

    const int tid  = threadIdx.x;
    const int lane = tid & 31;
    const int wid  = tid >> 5;
    const int tq   = lane & 3;
    const int tr   = lane >> 2;
    const int wcol = wid * 32;

    uint32_t B[4][8][2];
    #pragma unroll
    for (int nb = 0; nb < 4; nb++) {
        const int n = wcol + nb * 8 + tr;
        #pragma unroll
        for (int s = 0; s < 8; s++)
            #pragma unroll
            for (int hh = 0; hh < 2; hh++) {
                const int k0 = kofs + s * 16 + tq * 2 + hh * 8;
                B[nb][s][hh] = hfpair(W1[(size_t)k0 * HID + n],
                                      W1[(size_t)(k0 + 1) * HID + n]);
            }
    }

    const uint32_t ab = smem_u32(sA);
    const int r0  = lane & 15;
    const int hh0 = lane >> 4;

    for (int t = tid0; t < nTiles; t += tstr) {
        const int rbase = t * GROWS;

        #pragma unroll
        for (int p = 0; p < 16; p++) {
            const int i  = tid + p * 128;
            const int r  = i >> 5;
            const int f4 = i & 31;
            int rg = rbase + r; if (rg >= nrows) rg = nrows - 1;
            const float4 v = ((const float4*)(ztab + (size_t)rg * HID))[f4];
            const uint32_t h0 = hfpair(v.x, v.y), h1 = hfpair(v.z, v.w);
            const int c = f4 >> 1, hf = f4 & 1;
            const int cs = (c & 8) | ((c ^ r) & 7);
            *(uint2*)(sA + r * SR2 + cs * 16 + hf * 8) = make_uint2(h0, h1);
        }
        __syncthreads();

        float D[4][4][4];
        #pragma unroll
        for (int mb = 0; mb < 4; mb++)
            #pragma unroll
            for (int nb = 0; nb < 4; nb++)
                #pragma unroll
                for (int i = 0; i < 4; i++) D[mb][nb][i] = 0.f;

        #pragma unroll
        for (int s = 0; s < 8; s++) {
            const int c = 2 * s + hh0;
            uint32_t A[4][4];
            #pragma unroll
            for (int mb = 0; mb < 4; mb++) {
                const int r  = mb * 16 + r0;
                const int cs = (c & 8) | ((c ^ r) & 7);
                ldmat4(A[mb], ab + (uint32_t)(r * SR2 + cs * 16));
            }
            #pragma unroll
            for (int mb = 0; mb < 4; mb++)
                #pragma unroll
                for (int nb = 0; nb < 4; nb++)
                    mma16816(D[mb][nb], A[mb], B[nb][s][0], B[nb][s][1]);
        }

        #pragma unroll
        for (int mb = 0; mb < 4; mb++)
            #pragma unroll
            for (int nb = 0; nb < 4; nb++) {
                const int cp = (wcol >> 1) + nb * 4 + tq;
                float add0 = 0.f, add1 = 0.f;
                if (!isC) { add0 = b1f[2 * cp]; add1 = b1f[2 * cp + 1]; } // fold b1 into h_s
                const int r1 = rbase + mb * 16 + tr;
                const int r2 = r1 + 8;
                if (r1 < nrows) htab[(size_t)r1 * 64 + cp] =
                    hfpair(D[mb][nb][0] + add0, D[mb][nb][1] + add1);
                if (r2 < nrows) htab[(size_t)r2 * 64 + cp] =
                    hfpair(D[mb][nb][2] + add0, D[mb][nb][3] + add1);
            }
        __syncthreads();
    }
}

// ---------------- 2) bucket count ----------------
__global__ void __launch_bounds__(256)
count_k(const int* __restrict__ col, int E, int nB) {
    __shared__ int sc[NB_CAP];
    for (int i = threadIdx.x; i < nB; i += blockDim.x) sc[i] = 0;
    __syncthreads();
    for (int eg = blockIdx.x * blockDim.x + threadIdx.x; eg < E;
         eg += gridDim.x * blockDim.x)
        atomicAdd(&sc[col[eg] >> 6], 1);
    __syncthreads();
    for (int i = threadIdx.x; i < nB; i += blockDim.x)
        if (sc[i]) atomicAdd(&g_cnt[i], sc[i]);
}

// ---------------- 3) scan (1 CTA) ----------------
__global__ void __launch_bounds__(NB_CAP)
scan_k(int nB) {
    __shared__ int s[NB_CAP];
    const int t = threadIdx.x;
    s[t] = (t < nB) ? g_cnt[t] : 0;
    __syncthreads();
    #pragma unroll
    for (int d = 1; d < NB_CAP; d <<= 1) {
        int v = (t >= d) ? s[t - d] : 0;
        __syncthreads();
        s[t] += v;
        __syncthreads();
    }
    if (t < nB) {
        g_off[t + 1] = s[t];
        g_cur[t] = (t == 0) ? 0 : s[t - 1];
    }
    if (t == 0) g_off[0] = 0;
}

// ---------------- 4) scatter ----------------
__global__ void __launch_bounds__(256)
scatter_k(const int* __restrict__ row, const int* __restrict__ col, int E) {
    for (int eg = blockIdx.x * blockDim.x + threadIdx.x; eg < E;
         eg += gridDim.x * blockDim.x) {
        const int ci = col[eg];
        const int ri = row[eg];
        const int b  = ci >> 6;
        const int pos = atomicAdd(&g_cur[b], 1);
        g_rec[pos] = make_uint2(((uint32_t)ri << 6) | (uint32_t)(ci & 63), (uint32_t)eg);
    }
}

// ---------------- 5) bucketed edge pass ----------------
__global__ void __launch_bounds__(256)
edge_bkt(const float* __restrict__ W2f, const float* __restrict__ b2f,
         float* __restrict__ out, int nC, int nsU, int nB) {
    __shared__ __align__(16) char scr[64 * CROW];   // 17408 B
    const int tid = threadIdx.x;
    const int q   = tid & 7;

    float w2[16];
    #pragma unroll
    for (int j = 0; j < 8; j++) {
        w2[j]     = W2f[8 * q + j];
        w2[8 + j] = W2f[64 + 8 * q + j];
    }
    const float b2v = b2f[0];
    const __half2 zero = __float2half2_rn(0.f);
    const uint32_t* hS = g_h;
    const uint32_t* hC = g_h + (size_t)nsU;

    for (int b = blockIdx.x; b < nB; b += gridDim.x) {
        const int cbase = b << 6;
        __syncthreads();   // prior bucket's smem reads done
        for (int i = tid; i < 64 * 16; i += 256) {
            const int r = i >> 4, ch = i & 15;
            int cg = cbase + r; if (cg >= nC) cg = nC - 1;
            uint4 v = *(const uint4*)(hC + (size_t)cg * 64 + ch * 4);
            *(uint4*)(scr + r * CROW + ch * 16) = v;
        }
        __syncthreads();

        const int beg = g_off[b], end = g_off[b + 1];
        for (int i = beg + (tid >> 3); i < end; i += 32) {
            const uint2 rec = g_rec[i];
            const int ri  = rec.x >> 6;
            const int cil = rec.x & 63;
            const int eg  = (int)rec.y;

            const uint4* hs = (const uint4*)(hS + (size_t)ri * 64);
            uint4 a0 = hs[q], a1 = hs[q + 8];
            uint4 c0 = *(const uint4*)(scr + cil * CROW + q * 16);
            uint4 c1 = *(const uint4*)(scr + cil * CROW + 128 + q * 16);

            float acc = 0.f;
            const uint32_t* pa0 = &a0.x; const uint32_t* pc0 = &c0.x;
            const uint32_t* pa1 = &a1.x; const uint32_t* pc1 = &c1.x;
            #pragma unroll
            for (int j = 0; j < 4; j++) {
                __half2 h1 = __hmax2(__hadd2(*(const __half2*)&pa0[j],
                                             *(const __half2*)&pc0[j]), zero);
                __half2 h2 = __hmax2(__hadd2(*(const __half2*)&pa1[j],
                                             *(const __half2*)&pc1[j]), zero);
                float2 f1 = __half22float2(h1);
                float2 f2 = __half22float2(h2);
                acc = fmaf(f1.x, w2[2 * j], acc);
                acc = fmaf(f1.y, w2[2 * j + 1], acc);
                acc = fmaf(f2.x, w2[8 + 2 * j], acc);
                acc = fmaf(f2.y, w2[8 + 2 * j + 1], acc);
            }
            acc += __shfl_xor_sync(0xffffffffu, acc, 1);
            acc += __shfl_xor_sync(0xffffffffu, acc, 2);
            acc += __shfl_xor_sync(0xffffffffu, acc, 4);
            if (q == 0) out[eg] = acc + b2v;
        }
    }
}

extern "C" void kernel_launch(void* const* d_in, const int* in_sizes, int n_in,
                              void* d_out, int out_size)
{
    const float* zs  = (const float*)d_in[0];
    const float* zc  = (const float*)d_in[1];
    const int*   row = (const int*)d_in[2];
    const int*   col = (const int*)d_in[3];
    const float* W1  = (const float*)d_in[4];
    const float* b1  = (const float*)d_in[5];
    const float* W2  = (const float*)d_in[6];
    const float* b2  = (const float*)d_in[7];
    float* out = (float*)d_out;

    const int E  = in_sizes[2];
    const int nS = in_sizes[0] / HID;
    const int nC = in_sizes[1] / HID;
    const int nsU = nS * 64;
    const int nB  = (nC + 63) >> 6;

    int sms = 148;
    cudaDeviceGetAttribute(&sms, cudaDevAttrMultiProcessorCount, 0);

    // 1) persistent node GEMM (h_s has b1 folded in); also zeros bucket counters
    const int gridTot = 3 * sms;
    long long tot = (long long)nS + nC;
    int gridS = (int)((long long)gridTot * nS / tot);
    if (gridS < 1) gridS = 1;
    if (gridS > gridTot - 1) gridS = gridTot - 1;
    gemm_pre<<<gridTot, 128>>>(zs, zc, W1, b1, nS, nC, nsU, gridS, gridTot - gridS);

    // 2-4) bucket edges by course block
    count_k<<<2 * sms, 256>>>(col, E, nB);
    scan_k<<<1, NB_CAP>>>(nB);
    scatter_k<<<2 * sms, 256>>>(row, col, E);

    // 5) bucketed edge pass: course rows from smem, student rows from L2
    edge_bkt<<<nB, 256>>>(W2, b2, out, nC, nsU, nB);
}

// round 17
// speedup vs baseline: 4.0055x; 4.0055x over previous
#include <cuda_runtime.h>
#include <cuda_fp16.h>
#include <cstdint>

#define HID    128
#define NS_CAP 100096
#define NC_CAP 20096
__device__ uint32_t g_h[(NS_CAP + NC_CAP) * 64];  // fp16 h tables (f16x2 words)

// ---------------- helpers ----------------
__device__ __forceinline__ uint32_t smem_u32(const void* p) {
    uint32_t a;
    asm("{ .reg .u64 t; cvta.to.shared.u64 t, %1; cvt.u32.u64 %0, t; }" : "=r"(a) : "l"(p));
    return a;
}
__device__ __forceinline__ uint32_t hfpair(float lo, float hi) {
    uint32_t r;
    asm("cvt.rn.f16x2.f32 %0, %1, %2;" : "=r"(r) : "f"(hi), "f"(lo));
    return r;
}
__device__ __forceinline__ void ldmat4(uint32_t (&r)[4], uint32_t addr) {
    asm volatile("ldmatrix.sync.aligned.m8n8.x4.shared.b16 {%0,%1,%2,%3}, [%4];"
                 : "=r"(r[0]), "=r"(r[1]), "=r"(r[2]), "=r"(r[3]) : "r"(addr));
}
__device__ __forceinline__ void mma16816(float (&d)[4], const uint32_t (&a)[4],
                                         uint32_t b0, uint32_t b1) {
    asm volatile("mma.sync.aligned.m16n8k16.row.col.f32.f16.f16.f32 "
                 "{%0,%1,%2,%3}, {%4,%5,%6,%7}, {%8,%9}, {%0,%1,%2,%3};"
                 : "+f"(d[0]), "+f"(d[1]), "+f"(d[2]), "+f"(d[3])
                 : "r"(a[0]), "r"(a[1]), "r"(a[2]), "r"(a[3]), "r"(b0), "r"(b1));
}
#define CP_ASYNC16(dst, src) \
    asm volatile("cp.async.cg.shared.global [%0], [%1], 16;" :: "r"(dst), "l"(src) : "memory")
#define CP_COMMIT() asm volatile("cp.async.commit_group;" ::: "memory")
#define CP_WAIT(n)  asm volatile("cp.async.wait_group %0;" :: "n"(n) : "memory")

// ---------------- 1) persistent node GEMM, cp.async double-buffered ----------------
#define GROWS 64
#define SR2   256                        // fp16 tile row bytes
#define STG   (GROWS * 512)              // fp32 staging buffer bytes (32 KB)
#define OFF_H (2 * STG)                  // fp16 compute buffer offset
#define GSMEM (2 * STG + GROWS * SR2)    // 81920 B -> 2 CTAs/SM

__global__ void __launch_bounds__(128)
gemm_pre(const float* __restrict__ zs, const float* __restrict__ zc,
         const float* __restrict__ W1, const float* __restrict__ b1f,
         int nS, int nC, int nsU, int gridS, int gridC) {
    extern __shared__ __align__(16) char sm[];

    const bool isC  = blockIdx.x >= (unsigned)gridS;
    const int  tid0 = isC ? (blockIdx.x - gridS) : blockIdx.x;
    const int  tstr = isC ? gridC : gridS;
    const int  nrows = isC ? nC : nS;
    const int  nTiles = (nrows + GROWS - 1) / GROWS;
    const float* ztab = isC ? zc : zs;
    uint32_t*    htab = g_h + (isC ? (size_t)nsU : 0);
    const int kofs = isC ? HID : 0;

    const int tid  = threadIdx.x;
    const int lane = tid & 31;
    const int wid  = tid >> 5;
    const int tq   = lane & 3;
    const int tr   = lane >> 2;
    const int wcol = wid * 32;

    // B = W1 half fragments, built once per persistent CTA (64 regs)
    uint32_t B[4][8][2];
    #pragma unroll
    for (int nb = 0; nb < 4; nb++) {
        const int n = wcol + nb * 8 + tr;
        #pragma unroll
        for (int s = 0; s < 8; s++)
            #pragma unroll
            for (int hh = 0; hh < 2; hh++) {
                const int k0 = kofs + s * 16 + tq * 2 + hh * 8;
                B[nb][s][hh] = hfpair(W1[(size_t)k0 * HID + n],
                                      W1[(size_t)(k0 + 1) * HID + n]);
            }
    }

    const uint32_t smb = smem_u32(sm);
    const uint32_t hb  = smb + OFF_H;
    const int r0  = lane & 15;
    const int hh0 = lane >> 4;

    // stage a 64x128 fp32 tile via cp.async: 2048 x 16B chunks / 128 threads
    auto stage_tile = [&](int t, int idx) {
        const int rbase = t * GROWS;
        const uint32_t dst = smb + (uint32_t)idx * STG;
        #pragma unroll
        for (int p = 0; p < 16; p++) {
            const int i  = tid + p * 128;
            const int r  = i >> 5;                 // 32 chunks per 512B row
            const int ch = i & 31;
            int rg = rbase + r; if (rg >= nrows) rg = nrows - 1;
            CP_ASYNC16(dst + (uint32_t)(r * 512 + ch * 16),
                       (const char*)(ztab + (size_t)rg * HID) + ch * 16);
        }
        CP_COMMIT();
    };

    int t = tid0;
    int idx = 0;
    if (t < nTiles) stage_tile(t, 0);

    while (t < nTiles) {
        const int tn = t + tstr;
        if (tn < nTiles) { stage_tile(tn, idx ^ 1); CP_WAIT(1); }
        else             { CP_WAIT(0); }
        __syncthreads();   // stage[idx] visible; hbuf reads of prev tile done

        // convert fp32 staging -> fp16 swizzled compute buffer
        {
            const char* stg = sm + idx * STG;
            #pragma unroll
            for (int p = 0; p < 16; p++) {
                const int i  = tid + p * 128;
                const int r  = i >> 5;
                const int ch = i & 31;             // 16B fp32 chunk = 4 floats
                const float4 v = *(const float4*)(stg + r * 512 + ch * 16);
                const uint32_t h0 = hfpair(v.x, v.y), h1 = hfpair(v.z, v.w);
                const int c = ch >> 1, hf = ch & 1;
                const int cs = (c & 8) | ((c ^ r) & 7);
                *(uint2*)(sm + OFF_H + r * SR2 + cs * 16 + hf * 8) = make_uint2(h0, h1);
            }
        }
        __syncthreads();

        float D[4][4][4];
        #pragma unroll
        for (int mb = 0; mb < 4; mb++)
            #pragma unroll
            for (int nb = 0; nb < 4; nb++)
                #pragma unroll
                for (int i = 0; i < 4; i++) D[mb][nb][i] = 0.f;

        #pragma unroll
        for (int s = 0; s < 8; s++) {
            const int c = 2 * s + hh0;
            uint32_t A[4][4];
            #pragma unroll
            for (int mb = 0; mb < 4; mb++) {
                const int r  = mb * 16 + r0;
                const int cs = (c & 8) | ((c ^ r) & 7);
                ldmat4(A[mb], hb + (uint32_t)(r * SR2 + cs * 16));
            }
            #pragma unroll
            for (int mb = 0; mb < 4; mb++)
                #pragma unroll
                for (int nb = 0; nb < 4; nb++)
                    mma16816(D[mb][nb], A[mb], B[nb][s][0], B[nb][s][1]);
        }

        const int rbase = t * GROWS;
        #pragma unroll
        for (int mb = 0; mb < 4; mb++)
            #pragma unroll
            for (int nb = 0; nb < 4; nb++) {
                const int cp = (wcol >> 1) + nb * 4 + tq;
                float add0 = 0.f, add1 = 0.f;
                if (!isC) { add0 = b1f[2 * cp]; add1 = b1f[2 * cp + 1]; }  // fold b1 into h_s
                const int r1 = rbase + mb * 16 + tr;
                const int r2 = r1 + 8;
                if (r1 < nrows) htab[(size_t)r1 * 64 + cp] =
                    hfpair(D[mb][nb][0] + add0, D[mb][nb][1] + add1);
                if (r2 < nrows) htab[(size_t)r2 * 64 + cp] =
                    hfpair(D[mb][nb][2] + add0, D[mb][nb][3] + add1);
            }
        __syncthreads();   // ldsm reads of hbuf done before next conversion overwrites

        t = tn;
        idx ^= 1;
    }
}

// ---------------- 2) edge pass (R13 structure; b1 pre-folded into h_s) ----------------
__global__ void __launch_bounds__(256)
edge_out(const int* __restrict__ row, const int* __restrict__ col,
         const float* __restrict__ W2f, const float* __restrict__ b2f,
         float* __restrict__ out, int E, int nsU) {
    const int tid = threadIdx.x;
    const int q   = tid & 7;

    float w2[16];
    #pragma unroll
    for (int j = 0; j < 8; j++) {
        w2[j]     = W2f[8 * q + j];
        w2[8 + j] = W2f[64 + 8 * q + j];
    }
    const float b2v = b2f[0];
    const __half2 zero = __float2half2_rn(0.f);
    const uint32_t* hS = g_h;
    const uint32_t* hC = g_h + (size_t)nsU;

    const int slot  = (blockIdx.x * blockDim.x + tid) >> 3;
    const int nslot = (gridDim.x * blockDim.x) >> 3;

    for (int eg = slot; eg < E; eg += 2 * nslot) {
        const int eg2   = eg + nslot;
        const bool has2 = eg2 < E;

        const int ri  = row[eg];
        const int ci  = col[eg];
        const int ri2 = has2 ? row[eg2] : ri;
        const int ci2 = has2 ? col[eg2] : ci;

        const uint4* hs  = (const uint4*)(hS + (size_t)ri  * 64);
        const uint4* hc  = (const uint4*)(hC + (size_t)ci  * 64);
        const uint4* hs2 = (const uint4*)(hS + (size_t)ri2 * 64);
        const uint4* hc2 = (const uint4*)(hC + (size_t)ci2 * 64);
        uint4 a0 = hs[q],  a1 = hs[q + 8],  b0 = hc[q],  b1u = hc[q + 8];
        uint4 c0 = hs2[q], c1 = hs2[q + 8], d0 = hc2[q], d1 = hc2[q + 8];

        float acc1 = 0.f, acc2 = 0.f;
        const uint32_t* pa0 = &a0.x; const uint32_t* pb0 = &b0.x;
        const uint32_t* pa1 = &a1.x; const uint32_t* pb1 = &b1u.x;
        const uint32_t* pc0 = &c0.x; const uint32_t* pd0 = &d0.x;
        const uint32_t* pc1 = &c1.x; const uint32_t* pd1 = &d1.x;
        #pragma unroll
        for (int i = 0; i < 4; i++) {
            __half2 h1 = __hmax2(__hadd2(*(const __half2*)&pa0[i],
                                         *(const __half2*)&pb0[i]), zero);
            __half2 h2 = __hmax2(__hadd2(*(const __half2*)&pa1[i],
                                         *(const __half2*)&pb1[i]), zero);
            float2 f1 = __half22float2(h1);
            float2 f2 = __half22float2(h2);
            acc1 = fmaf(f1.x, w2[2 * i], acc1);
            acc1 = fmaf(f1.y, w2[2 * i + 1], acc1);
            acc1 = fmaf(f2.x, w2[8 + 2 * i], acc1);
            acc1 = fmaf(f2.y, w2[8 + 2 * i + 1], acc1);

            __half2 g1 = __hmax2(__hadd2(*(const __half2*)&pc0[i],
                                         *(const __half2*)&pd0[i]), zero);
            __half2 g2 = __hmax2(__hadd2(*(const __half2*)&pc1[i],
                                         *(const __half2*)&pd1[i]), zero);
            float2 e1 = __half22float2(g1);
            float2 e2 = __half22float2(g2);
            acc2 = fmaf(e1.x, w2[2 * i], acc2);
            acc2 = fmaf(e1.y, w2[2 * i + 1], acc2);
            acc2 = fmaf(e2.x, w2[8 + 2 * i], acc2);
            acc2 = fmaf(e2.y, w2[8 + 2 * i + 1], acc2);
        }
        #pragma unroll
        for (int m = 1; m <= 4; m <<= 1) {
            acc1 += __shfl_xor_sync(0xffffffffu, acc1, m);
            acc2 += __shfl_xor_sync(0xffffffffu, acc2, m);
        }
        if (q == 0) {
            out[eg] = acc1 + b2v;
            if (has2) out[eg2] = acc2 + b2v;
        }
    }
}

extern "C" void kernel_launch(void* const* d_in, const int* in_sizes, int n_in,
                              void* d_out, int out_size)
{
    const float* zs  = (const float*)d_in[0];
    const float* zc  = (const float*)d_in[1];
    const int*   row = (const int*)d_in[2];
    const int*   col = (const int*)d_in[3];
    const float* W1  = (const float*)d_in[4];
    const float* b1  = (const float*)d_in[5];
    const float* W2  = (const float*)d_in[6];
    const float* b2  = (const float*)d_in[7];
    float* out = (float*)d_out;

    const int E  = in_sizes[2];
    const int nS = in_sizes[0] / HID;
    const int nC = in_sizes[1] / HID;
    const int nsU = nS * 64;

    static bool attr_set = false;  // idempotent, not a work guard
    if (!attr_set) {
        cudaFuncSetAttribute(gemm_pre,
                             cudaFuncAttributeMaxDynamicSharedMemorySize, GSMEM);
        attr_set = true;
    }

    int sms = 148;
    cudaDeviceGetAttribute(&sms, cudaDevAttrMultiProcessorCount, 0);

    // 1) persistent node GEMM (cp.async pipelined; b1 folded into h_s)
    const int gridTot = 2 * sms;
    long long tot = (long long)nS + nC;
    int gridS = (int)((long long)gridTot * nS / tot);
    if (gridS < 1) gridS = 1;
    if (gridS > gridTot - 1) gridS = gridTot - 1;
    gemm_pre<<<gridTot, 128, GSMEM>>>(zs, zc, W1, b1, nS, nC, nsU,
                                      gridS, gridTot - gridS);

    // 2) edge pass
    edge_out<<<8 * sms, 256>>>(row, col, W2, b2, out, E, nsU);
}